// round 8
// baseline (speedup 1.0000x reference)
#include <cuda_runtime.h>
#include <cuda_bf16.h>
#include <cstdint>
#include <math.h>

#define BB 4
#define SS 1024
#define DD 1024
#define HH 16
#define INNER 16384
#define DI2 2048

// ---- scratch ----
__device__ float g_vals[BB * SS * DD];
__device__ float g_qkimg[BB * INNER];
__device__ float g_vv[BB * INNER];
__device__ float g_wq[BB * HH * DD];
__device__ float g_uq[BB * HH * DD];
__device__ float g_sim[BB * HH * SS];
__device__ float g_wvals[BB * HH * DD];
__device__ float g_wtext[BB * HH * DD];
__device__ float g_outpre[BB * INNER];
__device__ float g_ctxrow[BB * DD];
__device__ float g_h1[BB * DI2];
__device__ float g_h2[BB * DI2];
__device__ float g_trow[BB * DD];
__device__ __nv_bfloat16 g_Ahi[BB * SS * DD];
__device__ __nv_bfloat16 g_Alo[BB * SS * DD];
__device__ __nv_bfloat16 g_Bhi[DD * 3 * DD];
__device__ __nv_bfloat16 g_Blo[DD * 3 * DD];
__device__ __nv_bfloat16 g_qkvhi[BB * SS * 3 * DD];
__device__ __nv_bfloat16 g_qkvlo[BB * SS * 3 * DD];

// ---------------------------------------------------------------------------
__device__ __forceinline__ unsigned s2u(const void* p) {
    return (unsigned)__cvta_generic_to_shared(p);
}
__device__ __forceinline__ void ldsm_x4(unsigned* r, unsigned addr) {
    asm volatile("ldmatrix.sync.aligned.m8n8.x4.shared.b16 {%0,%1,%2,%3}, [%4];"
                 : "=r"(r[0]), "=r"(r[1]), "=r"(r[2]), "=r"(r[3]) : "r"(addr));
}
__device__ __forceinline__ void ldsm_x4t(unsigned* r, unsigned addr) {
    asm volatile("ldmatrix.sync.aligned.m8n8.x4.trans.shared.b16 {%0,%1,%2,%3}, [%4];"
                 : "=r"(r[0]), "=r"(r[1]), "=r"(r[2]), "=r"(r[3]) : "r"(addr));
}
__device__ __forceinline__ void mma_bf16(float* c, const unsigned* a,
                                         unsigned b0, unsigned b1) {
    asm volatile(
        "mma.sync.aligned.m16n8k16.row.col.f32.bf16.bf16.f32 "
        "{%0,%1,%2,%3}, {%4,%5,%6,%7}, {%8,%9}, {%0,%1,%2,%3};"
        : "+f"(c[0]), "+f"(c[1]), "+f"(c[2]), "+f"(c[3])
        : "r"(a[0]), "r"(a[1]), "r"(a[2]), "r"(a[3]), "r"(b0), "r"(b1));
}
__device__ __forceinline__ void cp16(unsigned dst, const void* src) {
    asm volatile("cp.async.cg.shared.global [%0], [%1], 16;" :: "r"(dst), "l"(src));
}
__device__ __forceinline__ void cp_commit() { asm volatile("cp.async.commit_group;"); }
__device__ __forceinline__ void cp_wait1() { asm volatile("cp.async.wait_group 1;"); }
__device__ __forceinline__ void cp_wait0() { asm volatile("cp.async.wait_group 0;"); }
__device__ __forceinline__ unsigned packbf(float x, float y) {
    unsigned short a = __bfloat16_as_ushort(__float2bfloat16(x));
    unsigned short b = __bfloat16_as_ushort(__float2bfloat16(y));
    return (unsigned)a | ((unsigned)b << 16);
}

// ---------------------------------------------------------------------------
__global__ void split2bf16(const float* __restrict__ x,
                           __nv_bfloat16* __restrict__ hi,
                           __nv_bfloat16* __restrict__ lo, int n4) {
    int i = blockIdx.x * 256 + threadIdx.x;
    if (i >= n4) return;
    float4 v = *(const float4*)&x[i * 4];
    __nv_bfloat16 h0 = __float2bfloat16(v.x);
    __nv_bfloat16 h1 = __float2bfloat16(v.y);
    __nv_bfloat16 h2 = __float2bfloat16(v.z);
    __nv_bfloat16 h3 = __float2bfloat16(v.w);
    *(__nv_bfloat162*)&hi[i * 4] = __halves2bfloat162(h0, h1);
    *(__nv_bfloat162*)&hi[i * 4 + 2] = __halves2bfloat162(h2, h3);
    *(__nv_bfloat162*)&lo[i * 4] = __halves2bfloat162(
        __float2bfloat16(v.x - __bfloat162float(h0)),
        __float2bfloat16(v.y - __bfloat162float(h1)));
    *(__nv_bfloat162*)&lo[i * 4 + 2] = __halves2bfloat162(
        __float2bfloat16(v.z - __bfloat162float(h2)),
        __float2bfloat16(v.w - __bfloat162float(h3)));
}

// ---------------------------------------------------------------------------
// bf16x3 tensor-core GEMM, 2-stage double buffer, 2 CTAs/SM.
#define LDA_S 40
#define LDB_S 136
#define STAGE_ELEMS (128 * LDA_S * 2 + 32 * LDB_S * 2)
#define GEMM_SMEM (2 * STAGE_ELEMS * 2)

#define LOAD_STAGE(S, K0)                                                              \
    do {                                                                               \
        __nv_bfloat16* _b = smem + (S) * STAGE_ELEMS;                                  \
        cp16(s2u(_b + aR0 * LDA_S + aC0), Ahi + (size_t)(rowBase + aR0) * K + (K0) + aC0); \
        cp16(s2u(_b + aR1 * LDA_S + aC1), Ahi + (size_t)(rowBase + aR1) * K + (K0) + aC1); \
        cp16(s2u(_b + 128 * LDA_S + aR0 * LDA_S + aC0), Alo + (size_t)(rowBase + aR0) * K + (K0) + aC0); \
        cp16(s2u(_b + 128 * LDA_S + aR1 * LDA_S + aC1), Alo + (size_t)(rowBase + aR1) * K + (K0) + aC1); \
        cp16(s2u(_b + 256 * LDA_S + bR0 * LDB_S + bC0), Bhi + (size_t)((K0) + bR0) * N + colBase + bC0); \
        cp16(s2u(_b + 256 * LDA_S + bR1 * LDB_S + bC1), Bhi + (size_t)((K0) + bR1) * N + colBase + bC1); \
        cp16(s2u(_b + 256 * LDA_S + 32 * LDB_S + bR0 * LDB_S + bC0), Blo + (size_t)((K0) + bR0) * N + colBase + bC0); \
        cp16(s2u(_b + 256 * LDA_S + 32 * LDB_S + bR1 * LDB_S + bC1), Blo + (size_t)((K0) + bR1) * N + colBase + bC1); \
        cp_commit();                                                                   \
    } while (0)

__global__ __launch_bounds__(256, 2) void gemm_bf16x3(
    const __nv_bfloat16* __restrict__ Ahi, const __nv_bfloat16* __restrict__ Alo,
    const __nv_bfloat16* __restrict__ Bhi, const __nv_bfloat16* __restrict__ Blo,
    const float* __restrict__ bias,
    __nv_bfloat16* __restrict__ Chi, __nv_bfloat16* __restrict__ Clo,
    int M, int N, int K) {
    extern __shared__ char dynsm[];
    __nv_bfloat16* smem = (__nv_bfloat16*)dynsm;
    const int tid = threadIdx.x;
    const int warp = tid >> 5, lane = tid & 31;
    const int wm = (warp >> 2) * 64, wn = (warp & 3) * 32;
    const int rowBase = blockIdx.y * 128, colBase = blockIdx.x * 128;

    const int aR0 = (tid * 2) >> 2, aC0 = ((tid * 2) & 3) << 3;
    const int aR1 = (tid * 2 + 1) >> 2, aC1 = ((tid * 2 + 1) & 3) << 3;
    const int bR0 = (tid * 2) >> 4, bC0 = ((tid * 2) & 15) << 3;
    const int bR1 = (tid * 2 + 1) >> 4, bC1 = ((tid * 2 + 1) & 15) << 3;

    float cacc[4][4][4];
#pragma unroll
    for (int i = 0; i < 4; i++)
#pragma unroll
        for (int j = 0; j < 4; j++)
#pragma unroll
            for (int v = 0; v < 4; v++) cacc[i][j][v] = 0.f;

    const int nIter = K / 32;
    LOAD_STAGE(0, 0);

    for (int it = 0; it < nIter; it++) {
        if (it + 1 < nIter) {
            LOAD_STAGE((it + 1) & 1, (it + 1) * 32);
            cp_wait1();
        } else {
            cp_wait0();
        }
        __syncthreads();
        const int cur = it & 1;
        __nv_bfloat16* sAh = smem + cur * STAGE_ELEMS;
        __nv_bfloat16* sAl = sAh + 128 * LDA_S;
        __nv_bfloat16* sBh = sAh + 256 * LDA_S;
        __nv_bfloat16* sBl = sAh + 256 * LDA_S + 32 * LDB_S;

#pragma unroll
        for (int ks = 0; ks < 32; ks += 16) {
            unsigned ah[4][4], al[4][4], bh[2][4], bl[2][4];
            const int arow = (lane & 15);
            const int acol = ks + ((lane >> 4) << 3);
#pragma unroll
            for (int mt = 0; mt < 4; mt++) {
                int off = (wm + mt * 16 + arow) * LDA_S + acol;
                ldsm_x4(ah[mt], s2u(sAh + off));
                ldsm_x4(al[mt], s2u(sAl + off));
            }
            const int brow = ks + (lane & 15);
            const int bcol0 = wn + ((lane >> 4) << 3);
#pragma unroll
            for (int nt = 0; nt < 2; nt++) {
                int off = brow * LDB_S + bcol0 + nt * 16;
                ldsm_x4t(bh[nt], s2u(sBh + off));
                ldsm_x4t(bl[nt], s2u(sBl + off));
            }
#pragma unroll
            for (int mt = 0; mt < 4; mt++) {
#pragma unroll
                for (int j = 0; j < 4; j++) {
                    unsigned bh0 = bh[j >> 1][(j & 1) * 2], bh1 = bh[j >> 1][(j & 1) * 2 + 1];
                    unsigned bl0 = bl[j >> 1][(j & 1) * 2], bl1 = bl[j >> 1][(j & 1) * 2 + 1];
                    mma_bf16(cacc[mt][j], ah[mt], bh0, bh1);
                    mma_bf16(cacc[mt][j], ah[mt], bl0, bl1);
                    mma_bf16(cacc[mt][j], al[mt], bh0, bh1);
                }
            }
        }
        __syncthreads();   // protect cur buffer before next prefetch overwrites it
    }

#pragma unroll
    for (int mt = 0; mt < 4; mt++) {
#pragma unroll
        for (int j = 0; j < 4; j++) {
            int r0 = rowBase + wm + mt * 16 + (lane >> 2);
            int c0 = colBase + wn + j * 8 + (lane & 3) * 2;
            float b0 = bias[c0], b1 = bias[c0 + 1];
#pragma unroll
            for (int half = 0; half < 2; half++) {
                int r = r0 + half * 8;
                float x = cacc[mt][j][half * 2 + 0] + b0;
                float y = cacc[mt][j][half * 2 + 1] + b1;
                __nv_bfloat16 hx = __float2bfloat16(x);
                __nv_bfloat16 hy = __float2bfloat16(y);
                *(__nv_bfloat162*)&Chi[(size_t)r * N + c0] = __halves2bfloat162(hx, hy);
                *(__nv_bfloat162*)&Clo[(size_t)r * N + c0] = __halves2bfloat162(
                    __float2bfloat16(x - __bfloat162float(hx)),
                    __float2bfloat16(y - __bfloat162float(hy)));
            }
        }
    }
}

// ---------------------------------------------------------------------------
// Tensor-core flash attention (bf16x3). Scale 0.125 folded into exp/max.
#define SA 72
#define ATT_STAGE (4 * 64 * SA)
#define ATT_SMEM ((2 * 64 * SA + 2 * ATT_STAGE) * 2)

__global__ __launch_bounds__(128) void attn3(const __nv_bfloat16* __restrict__ qkvhi,
                                             const __nv_bfloat16* __restrict__ qkvlo,
                                             float* __restrict__ vals) {
    extern __shared__ char dynsm[];
    __nv_bfloat16* SM = (__nv_bfloat16*)dynsm;
    __nv_bfloat16* Qhi = SM;
    __nv_bfloat16* Qlo = SM + 64 * SA;
    const int tid = threadIdx.x;
    const int warp = tid >> 5, lane = tid & 31;
    const int b = blockIdx.x >> 4, h = blockIdx.x & 15;
    const int qbase = blockIdx.y * 64;
    const size_t gbase = (size_t)b * SS * 3072 + h * 192;

    {
#pragma unroll
        for (int i = 0; i < 4; i++) {
            int c = i * 128 + tid;
            int row = c >> 3, col = (c & 7) << 3;
            size_t src = gbase + (size_t)(qbase + row) * 3072 + col;
            cp16(s2u(Qhi + row * SA + col), qkvhi + src);
            cp16(s2u(Qlo + row * SA + col), qkvlo + src);
        }
        __nv_bfloat16* st = SM + 2 * 64 * SA;
#pragma unroll
        for (int i = 0; i < 4; i++) {
            int c = i * 128 + tid;
            int row = c >> 3, col = (c & 7) << 3;
            size_t srcK = gbase + (size_t)row * 3072 + 64 + col;
            size_t srcV = gbase + (size_t)row * 3072 + 128 + col;
            cp16(s2u(st + row * SA + col), qkvhi + srcK);
            cp16(s2u(st + 64 * SA + row * SA + col), qkvlo + srcK);
            cp16(s2u(st + 2 * 64 * SA + row * SA + col), qkvhi + srcV);
            cp16(s2u(st + 3 * 64 * SA + row * SA + col), qkvlo + srcV);
        }
        cp_commit();
    }

    unsigned qh[4][4], ql[4][4];
    float o[8][4];
    float m0 = -1e30f, m1 = -1e30f, l0 = 0.f, l1 = 0.f;   // m on RAW score domain
#pragma unroll
    for (int i = 0; i < 8; i++)
#pragma unroll
        for (int j = 0; j < 4; j++) o[i][j] = 0.f;

    const int NT = SS / 64;
    for (int t = 0; t < NT; t++) {
        const int cur = t & 1;
        if (t + 1 < NT) {
            __nv_bfloat16* st = SM + 2 * 64 * SA + (cur ^ 1) * ATT_STAGE;
            const int kv0 = (t + 1) * 64;
#pragma unroll
            for (int i = 0; i < 4; i++) {
                int c = i * 128 + tid;
                int row = c >> 3, col = (c & 7) << 3;
                size_t srcK = gbase + (size_t)(kv0 + row) * 3072 + 64 + col;
                size_t srcV = gbase + (size_t)(kv0 + row) * 3072 + 128 + col;
                cp16(s2u(st + row * SA + col), qkvhi + srcK);
                cp16(s2u(st + 64 * SA + row * SA + col), qkvlo + srcK);
                cp16(s2u(st + 2 * 64 * SA + row * SA + col), qkvhi + srcV);
                cp16(s2u(st + 3 * 64 * SA + row * SA + col), qkvlo + srcV);
            }
            cp_commit();
            cp_wait1();
        } else {
            cp_wait0();
        }
        __syncthreads();

        if (t == 0) {
#pragma unroll
            for (int kt = 0; kt < 4; kt++) {
                int off = (warp * 16 + (lane & 15)) * SA + kt * 16 + ((lane >> 4) << 3);
                ldsm_x4(qh[kt], s2u(Qhi + off));
                ldsm_x4(ql[kt], s2u(Qlo + off));
            }
        }

        __nv_bfloat16* sKh = SM + 2 * 64 * SA + cur * ATT_STAGE;
        __nv_bfloat16* sKl = sKh + 64 * SA;
        __nv_bfloat16* sVh = sKh + 2 * 64 * SA;
        __nv_bfloat16* sVl = sKh + 3 * 64 * SA;

        float sc[8][4];
#pragma unroll
        for (int n = 0; n < 8; n++)
#pragma unroll
            for (int v = 0; v < 4; v++) sc[n][v] = 0.f;
#pragma unroll
        for (int kt = 0; kt < 4; kt++) {
            unsigned kh[4][4], kl[4][4];
#pragma unroll
            for (int nt = 0; nt < 4; nt++) {
                int off = (nt * 16 + (lane & 15)) * SA + kt * 16 + ((lane >> 4) << 3);
                ldsm_x4(kh[nt], s2u(sKh + off));
                ldsm_x4(kl[nt], s2u(sKl + off));
            }
#pragma unroll
            for (int nt = 0; nt < 4; nt++) {
#pragma unroll
                for (int sub = 0; sub < 2; sub++) {
                    int n = nt * 2 + sub;
                    mma_bf16(sc[n], qh[kt], kh[nt][sub], kh[nt][sub + 2]);
                    mma_bf16(sc[n], qh[kt], kl[nt][sub], kl[nt][sub + 2]);
                    mma_bf16(sc[n], ql[kt], kh[nt][sub], kh[nt][sub + 2]);
                }
            }
        }

        // online softmax on raw-score domain; exp uses fused 0.125 scale
        float mt0 = -1e30f, mt1 = -1e30f;
#pragma unroll
        for (int n = 0; n < 8; n++) {
            mt0 = fmaxf(mt0, fmaxf(sc[n][0], sc[n][1]));
            mt1 = fmaxf(mt1, fmaxf(sc[n][2], sc[n][3]));
        }
        mt0 = fmaxf(mt0, __shfl_xor_sync(0xffffffffu, mt0, 1));
        mt0 = fmaxf(mt0, __shfl_xor_sync(0xffffffffu, mt0, 2));
        mt1 = fmaxf(mt1, __shfl_xor_sync(0xffffffffu, mt1, 1));
        mt1 = fmaxf(mt1, __shfl_xor_sync(0xffffffffu, mt1, 2));
        float mn0 = fmaxf(m0, mt0), mn1 = fmaxf(m1, mt1);
        float cr0 = __expf(0.125f * (m0 - mn0));
        float cr1 = __expf(0.125f * (m1 - mn1));
        float nb0 = -0.125f * mn0, nb1 = -0.125f * mn1;
        float s0 = 0.f, s1 = 0.f;
#pragma unroll
        for (int n = 0; n < 8; n++) {
            sc[n][0] = __expf(fmaf(sc[n][0], 0.125f, nb0));
            sc[n][1] = __expf(fmaf(sc[n][1], 0.125f, nb0));
            sc[n][2] = __expf(fmaf(sc[n][2], 0.125f, nb1));
            sc[n][3] = __expf(fmaf(sc[n][3], 0.125f, nb1));
            s0 += sc[n][0] + sc[n][1];
            s1 += sc[n][2] + sc[n][3];
        }
        s0 += __shfl_xor_sync(0xffffffffu, s0, 1);
        s0 += __shfl_xor_sync(0xffffffffu, s0, 2);
        s1 += __shfl_xor_sync(0xffffffffu, s1, 1);
        s1 += __shfl_xor_sync(0xffffffffu, s1, 2);
        l0 = l0 * cr0 + s0; l1 = l1 * cr1 + s1;
        m0 = mn0; m1 = mn1;
#pragma unroll
        for (int d = 0; d < 8; d++) {
            o[d][0] *= cr0; o[d][1] *= cr0;
            o[d][2] *= cr1; o[d][3] *= cr1;
        }

        unsigned ph[4][4], pl[4][4];
#pragma unroll
        for (int kt2 = 0; kt2 < 4; kt2++) {
#pragma unroll
            for (int part = 0; part < 4; part++) {
                int n = kt2 * 2 + (part >> 1);
                int i0 = (part & 1) * 2;
                float x = sc[n][i0], y = sc[n][i0 + 1];
                __nv_bfloat16 hx = __float2bfloat16(x);
                __nv_bfloat16 hy = __float2bfloat16(y);
                ph[kt2][part] = (unsigned)__bfloat16_as_ushort(hx) |
                                ((unsigned)__bfloat16_as_ushort(hy) << 16);
                pl[kt2][part] = packbf(x - __bfloat162float(hx),
                                       y - __bfloat162float(hy));
            }
        }

#pragma unroll
        for (int kt2 = 0; kt2 < 4; kt2++) {
            unsigned vh[4][4], vl[4][4];
#pragma unroll
            for (int dt = 0; dt < 4; dt++) {
                int off = (kt2 * 16 + (lane & 15)) * SA + dt * 16 + ((lane >> 4) << 3);
                ldsm_x4t(vh[dt], s2u(sVh + off));
                ldsm_x4t(vl[dt], s2u(sVl + off));
            }
#pragma unroll
            for (int dt = 0; dt < 4; dt++) {
#pragma unroll
                for (int sub = 0; sub < 2; sub++) {
                    int d = dt * 2 + sub;
                    mma_bf16(o[d], ph[kt2], vh[dt][sub * 2], vh[dt][sub * 2 + 1]);
                    mma_bf16(o[d], ph[kt2], vl[dt][sub * 2], vl[dt][sub * 2 + 1]);
                    mma_bf16(o[d], pl[kt2], vh[dt][sub * 2], vh[dt][sub * 2 + 1]);
                }
            }
        }
        __syncthreads();
    }

    float inv0 = 1.f / l0, inv1 = 1.f / l1;
    int row0 = qbase + warp * 16 + (lane >> 2);
    int row1 = row0 + 8;
#pragma unroll
    for (int d = 0; d < 8; d++) {
        int c0 = h * 64 + d * 8 + (lane & 3) * 2;
        float2 v0; v0.x = o[d][0] * inv0; v0.y = o[d][1] * inv0;
        float2 v1; v1.x = o[d][2] * inv1; v1.y = o[d][3] * inv1;
        *(float2*)&vals[(size_t)(b * SS + row0) * DD + c0] = v0;
        *(float2*)&vals[(size_t)(b * SS + row1) * DD + c0] = v1;
    }
}

// ---------------------------------------------------------------------------
__global__ void init_all(float* __restrict__ qkimg, float* __restrict__ vv,
                         float* __restrict__ outpre, float* __restrict__ wvals,
                         float* __restrict__ h1, float* __restrict__ h2,
                         float* __restrict__ trow,
                         float* __restrict__ outh, const float* __restrict__ out_b,
                         float* __restrict__ ctxrow, const float* __restrict__ ctx_out_b,
                         float* __restrict__ wtext, const float* __restrict__ o_b) {
    int i = blockIdx.x * 256 + threadIdx.x;
    qkimg[i] = 0.f; vv[i] = 0.f; outpre[i] = 0.f; wvals[i] = 0.f;
    wtext[i] = o_b[i & 1023];
    if (i < BB * DI2) { h1[i] = 0.f; h2[i] = 0.f; }
    if (i < BB * DD) {
        trow[i] = 0.f;
        outh[i] = out_b[i & 1023];
        ctxrow[i] = ctx_out_b[i & 1023];
    }
}

// ---------------------------------------------------------------------------
__global__ void img_proj(const float* __restrict__ img,
                         const float* __restrict__ W1, const float* __restrict__ W2,
                         float* __restrict__ O1, float* __restrict__ O2) {
    const float* W = blockIdx.z ? W2 : W1;
    float* O = blockIdx.z ? O2 : O1;
    int col = blockIdx.x * 256 + threadIdx.x;
    int k0 = blockIdx.y * 128;
    __shared__ float xs[4][128];
    for (int i = threadIdx.x; i < 512; i += 256)
        xs[i >> 7][i & 127] = img[(i >> 7) * DD + k0 + (i & 127)];
    __syncthreads();
    float a0 = 0, a1 = 0, a2 = 0, a3 = 0;
    const float* wp = W + (size_t)k0 * INNER + col;
#pragma unroll 4
    for (int k = 0; k < 128; k++) {
        float wv = wp[(size_t)k * INNER];
        a0 += xs[0][k] * wv; a1 += xs[1][k] * wv;
        a2 += xs[2][k] * wv; a3 += xs[3][k] * wv;
    }
    atomicAdd(&O[col], a0);
    atomicAdd(&O[INNER + col], a1);
    atomicAdd(&O[2 * INNER + col], a2);
    atomicAdd(&O[3 * INNER + col], a3);
}

// ---------------------------------------------------------------------------
__global__ __launch_bounds__(256) void wq_kernel(const float* __restrict__ Wc,
                                                 const float* __restrict__ qkimg,
                                                 float* __restrict__ wq) {
    int gwarp = (blockIdx.x * 256 + threadIdx.x) >> 5;
    int lane = threadIdx.x & 31;
    int d = gwarp >> 4, h = gwarp & 15;
    const float* row = Wc + (size_t)d * INNER + h * 1024;
    const float* qb = qkimg + h * 1024;
    float a0 = 0, a1 = 0, a2 = 0, a3 = 0;
    for (int e = lane; e < 1024; e += 32) {
        float wv = row[e];
        a0 += wv * qb[e];
        a1 += wv * qb[INNER + e];
        a2 += wv * qb[2 * INNER + e];
        a3 += wv * qb[3 * INNER + e];
    }
#pragma unroll
    for (int o = 16; o; o >>= 1) {
        a0 += __shfl_xor_sync(0xffffffffu, a0, o);
        a1 += __shfl_xor_sync(0xffffffffu, a1, o);
        a2 += __shfl_xor_sync(0xffffffffu, a2, o);
        a3 += __shfl_xor_sync(0xffffffffu, a3, o);
    }
    if (lane == 0) {
        wq[(0 * HH + h) * DD + d] = a0;
        wq[(1 * HH + h) * DD + d] = a1;
        wq[(2 * HH + h) * DD + d] = a2;
        wq[(3 * HH + h) * DD + d] = a3;
    }
}

// ---------------------------------------------------------------------------
template <int MT>
__global__ __launch_bounds__(256) void gemm_nt(const float* __restrict__ A, int lda, long sA,
                                               const float* __restrict__ Bm, int ldb, long sB,
                                               float* __restrict__ C, int ldc, long sC,
                                               int M, int N, int K, float alpha) {
    int batch = blockIdx.y;
    A += (size_t)batch * sA; Bm += (size_t)batch * sB; C += (size_t)batch * sC;
    int warp = threadIdx.x >> 5, lane = threadIdx.x & 31;
    int j = blockIdx.x * 8 + warp;
    __shared__ float As[MT][128];
    float acc[MT];
#pragma unroll
    for (int i = 0; i < MT; i++) acc[i] = 0.f;
    for (int k0 = 0; k0 < K; k0 += 128) {
        __syncthreads();
        for (int i = threadIdx.x; i < MT * 128; i += 256) {
            int r = i >> 7, c = i & 127;
            As[r][c] = (r < M) ? A[(size_t)r * lda + k0 + c] : 0.f;
        }
        __syncthreads();
        const float* bp = Bm + (size_t)j * ldb + k0;
        for (int k = lane; k < 128; k += 32) {
            float bv = bp[k];
#pragma unroll
            for (int i = 0; i < MT; i++) acc[i] += As[i][k] * bv;
        }
    }
#pragma unroll
    for (int i = 0; i < MT; i++) {
        float v = acc[i];
#pragma unroll
        for (int o = 16; o; o >>= 1) v += __shfl_xor_sync(0xffffffffu, v, o);
        if (lane == 0 && i < M) C[(size_t)i * ldc + j] = alpha * v;
    }
}

// ---------------------------------------------------------------------------
template <int MT>
__global__ __launch_bounds__(256) void gemm_nn(const float* __restrict__ A, int lda, long sA,
                                               const float* __restrict__ Bm, int ldb, long sB,
                                               const float* __restrict__ bias,
                                               float* __restrict__ C, int ldc, long sC,
                                               int M, int N, int K, float alpha, int act) {
    int batch = blockIdx.y;
    A += (size_t)batch * sA; Bm += (size_t)batch * sB; C += (size_t)batch * sC;
    int j = blockIdx.x * 256 + threadIdx.x;
    int kChunk = K / gridDim.z;
    int kBeg = blockIdx.z * kChunk;
    float acc[MT];
#pragma unroll
    for (int i = 0; i < MT; i++) acc[i] = 0.f;
    __shared__ float As[MT][32];
    for (int k0 = kBeg; k0 < kBeg + kChunk; k0 += 32) {
        __syncthreads();
        for (int i = threadIdx.x; i < MT * 32; i += 256) {
            int r = i >> 5, c = i & 31;
            As[r][c] = (r < M) ? A[(size_t)r * lda + k0 + c] : 0.f;
        }
        __syncthreads();
#pragma unroll 4
        for (int k = 0; k < 32; k++) {
            float bv = Bm[(size_t)(k0 + k) * ldb + j];
#pragma unroll
            for (int i = 0; i < MT; i++) acc[i] += As[i][k] * bv;
        }
    }
    if (gridDim.z == 1) {
        float bb = bias ? bias[j] : 0.f;
        for (int i = 0; i < MT && i < M; i++) {
            float v = alpha * acc[i] + bb;
            if (act) v = tanhf(v);
            C[(size_t)i * ldc + j] = v;
        }
    } else {
        for (int i = 0; i < MT && i < M; i++)
            atomicAdd(&C[(size_t)i * ldc + j], alpha * acc[i]);
    }
}

// ---------------------------------------------------------------------------
template <int MT>
__global__ __launch_bounds__(256) void gemm_nn4(const float* __restrict__ A, int lda, long sA,
                                                const float* __restrict__ Bm, int ldb, long sB,
                                                float* __restrict__ C, int ldc, long sC,
                                                int M, int K) {
    int batch = blockIdx.y;
    A += (size_t)batch * sA; Bm += (size_t)batch * sB; C += (size_t)batch * sC;
    int j4 = (blockIdx.x * 256 + threadIdx.x) * 4;
    int kChunk = K / gridDim.z;
    int kBeg = blockIdx.z * kChunk;
    float acc[MT][4];
#pragma unroll
    for (int i = 0; i < MT; i++) {
        acc[i][0] = 0.f; acc[i][1] = 0.f; acc[i][2] = 0.f; acc[i][3] = 0.f;
    }
    __shared__ float As[MT][32];
    for (int k0 = kBeg; k0 < kBeg + kChunk; k0 += 32) {
        __syncthreads();
        for (int i = threadIdx.x; i < MT * 32; i += 256) {
            int r = i >> 5, c = i & 31;
            As[r][c] = (r < M) ? A[(size_t)r * lda + k0 + c] : 0.f;
        }
        __syncthreads();
#pragma unroll 8
        for (int k = 0; k < 32; k++) {
            float4 bv = *(const float4*)&Bm[(size_t)(k0 + k) * ldb + j4];
#pragma unroll
            for (int i = 0; i < MT; i++) {
                float a = As[i][k];
                acc[i][0] += a * bv.x; acc[i][1] += a * bv.y;
                acc[i][2] += a * bv.z; acc[i][3] += a * bv.w;
            }
        }
    }
    for (int i = 0; i < MT && i < M; i++) {
        atomicAdd(&C[(size_t)i * ldc + j4 + 0], acc[i][0]);
        atomicAdd(&C[(size_t)i * ldc + j4 + 1], acc[i][1]);
        atomicAdd(&C[(size_t)i * ldc + j4 + 2], acc[i][2]);
        atomicAdd(&C[(size_t)i * ldc + j4 + 3], acc[i][3]);
    }
}

// ---------------------------------------------------------------------------
__global__ void softmax_rows(float* __restrict__ base, int n) {
    float* p = base + (size_t)blockIdx.x * n;
    __shared__ float red[8];
    __shared__ float red2[8];
    int tid = threadIdx.x;
    float m = -1e30f;
    for (int j = tid; j < n; j += 256) m = fmaxf(m, p[j]);
#pragma unroll
    for (int o = 16; o; o >>= 1) m = fmaxf(m, __shfl_xor_sync(0xffffffffu, m, o));
    if ((tid & 31) == 0) red[tid >> 5] = m;
    __syncthreads();
    float mm = red[0];
#pragma unroll
    for (int w = 1; w < 8; w++) mm = fmaxf(mm, red[w]);
    float sum = 0.f;
    for (int j = tid; j < n; j += 256) {
        float e = __expf(p[j] - mm);
        p[j] = e;
        sum += e;
    }
#pragma unroll
    for (int o = 16; o; o >>= 1) sum += __shfl_xor_sync(0xffffffffu, sum, o);
    if ((tid & 31) == 0) red2[tid >> 5] = sum;
    __syncthreads();
    float tot = 0.f;
#pragma unroll
    for (int w = 0; w < 8; w++) tot += red2[w];
    float inv = 1.f / tot;
    for (int j = tid; j < n; j += 256) p[j] *= inv;
}

// ---------------------------------------------------------------------------
__global__ void tanh_bias_k(float* __restrict__ x, const float* __restrict__ bias,
                            int n, int total) {
    int i = blockIdx.x * 256 + threadIdx.x;
    if (i < total) x[i] = tanhf(x[i] + bias[i % n]);
}

__global__ void bcast_text(const float* __restrict__ trow, const float* __restrict__ b3,
                           float* __restrict__ out) {
    size_t idx = (size_t)blockIdx.x * 256 + threadIdx.x;
    size_t e = idx * 4;
    int b = (int)(e / ((size_t)SS * DD));
    int d = (int)(e % DD);
    float4 t = *(const float4*)&trow[b * DD + d];
    float4 bb = *(const float4*)&b3[d];
    t.x += bb.x; t.y += bb.y; t.z += bb.z; t.w += bb.w;
    *(float4*)&out[e] = t;
}

// ---------------------------------------------------------------------------
extern "C" void kernel_launch(void* const* d_in, const int* in_sizes, int n_in,
                              void* d_out, int out_size) {
    (void)in_sizes; (void)n_in; (void)out_size;
    const float* img      = (const float*)d_in[0];
    const float* text_emb = (const float*)d_in[1];
    const float* qkv_w    = (const float*)d_in[2];
    const float* qkv_b    = (const float*)d_in[3];
    const float* o_w      = (const float*)d_in[4];
    const float* o_b      = (const float*)d_in[5];
    const float* qk_w     = (const float*)d_in[6];
    const float* ctx_qk_w = (const float*)d_in[7];
    const float* v_w      = (const float*)d_in[8];
    const float* ctx_v_w  = (const float*)d_in[9];
    const float* out_w    = (const float*)d_in[10];
    const float* out_b    = (const float*)d_in[11];
    const float* ctx_out_w= (const float*)d_in[12];
    const float* ctx_out_b= (const float*)d_in[13];
    const float* w1 = (const float*)d_in[14];
    const float* b1 = (const float*)d_in[15];
    const float* w2 = (const float*)d_in[16];
    const float* b2 = (const float*)d_in[17];
    const float* w3 = (const float*)d_in[18];
    const float* b3 = (const float*)d_in[19];

    float* out_head = (float*)d_out;
    float* out_text = (float*)d_out + BB * DD;

    float* p_vals;   cudaGetSymbolAddress((void**)&p_vals, g_vals);
    float* p_qkimg;  cudaGetSymbolAddress((void**)&p_qkimg, g_qkimg);
    float* p_vv;     cudaGetSymbolAddress((void**)&p_vv, g_vv);
    float* p_wq;     cudaGetSymbolAddress((void**)&p_wq, g_wq);
    float* p_uq;     cudaGetSymbolAddress((void**)&p_uq, g_uq);
    float* p_sim;    cudaGetSymbolAddress((void**)&p_sim, g_sim);
    float* p_wvals;  cudaGetSymbolAddress((void**)&p_wvals, g_wvals);
    float* p_wtext;  cudaGetSymbolAddress((void**)&p_wtext, g_wtext);
    float* p_outpre; cudaGetSymbolAddress((void**)&p_outpre, g_outpre);
    float* p_ctxrow; cudaGetSymbolAddress((void**)&p_ctxrow, g_ctxrow);
    float* p_h1;     cudaGetSymbolAddress((void**)&p_h1, g_h1);
    float* p_h2;     cudaGetSymbolAddress((void**)&p_h2, g_h2);
    float* p_trow;   cudaGetSymbolAddress((void**)&p_trow, g_trow);
    __nv_bfloat16* p_Ahi; cudaGetSymbolAddress((void**)&p_Ahi, g_Ahi);
    __nv_bfloat16* p_Alo; cudaGetSymbolAddress((void**)&p_Alo, g_Alo);
    __nv_bfloat16* p_Bhi; cudaGetSymbolAddress((void**)&p_Bhi, g_Bhi);
    __nv_bfloat16* p_Blo; cudaGetSymbolAddress((void**)&p_Blo, g_Blo);
    __nv_bfloat16* p_Qkvhi; cudaGetSymbolAddress((void**)&p_Qkvhi, g_qkvhi);
    __nv_bfloat16* p_Qkvlo; cudaGetSymbolAddress((void**)&p_Qkvlo, g_qkvlo);

    static bool attr_set = false;
    if (!attr_set) {
        cudaFuncSetAttribute((const void*)attn3,
                             cudaFuncAttributeMaxDynamicSharedMemorySize, ATT_SMEM);
        cudaFuncSetAttribute((const void*)gemm_bf16x3,
                             cudaFuncAttributeMaxDynamicSharedMemorySize, GEMM_SMEM);
        attr_set = true;
    }

    // 0: fused inits (moved first so gemm lands at profiled idx 3)
    init_all<<<256, 256>>>(p_qkimg, p_vv, p_outpre, p_wvals, p_h1, p_h2, p_trow,
                           out_head, out_b, p_ctxrow, ctx_out_b, p_wtext, o_b);
    // 1-2: splits
    split2bf16<<<(BB * SS * DD / 4 + 255) / 256, 256>>>(text_emb, p_Ahi, p_Alo,
                                                        BB * SS * DD / 4);
    split2bf16<<<(DD * 3 * DD / 4 + 255) / 256, 256>>>(qkv_w, p_Bhi, p_Blo,
                                                       DD * 3 * DD / 4);
    // 3: QKV GEMM (PROFILED: launch index 3), 2 CTAs/SM
    gemm_bf16x3<<<dim3(3072 / 128, 4096 / 128), 256, GEMM_SMEM>>>(
        p_Ahi, p_Alo, p_Bhi, p_Blo, qkv_b, p_Qkvhi, p_Qkvlo, BB * SS, 3 * DD, DD);
    // 4: tensor-core flash attention
    attn3<<<dim3(BB * HH, SS / 64), 128, ATT_SMEM>>>(p_Qkvhi, p_Qkvlo, p_vals);
    // 5: img projections
    img_proj<<<dim3(INNER / 256, 8, 2), 256>>>(img, qk_w, v_w, p_qkimg, p_vv);
    // 6: wq
    wq_kernel<<<2048, 256>>>(ctx_qk_w, p_qkimg, p_wq);
    // 7: uq
    gemm_nt<64><<<dim3(DD / 8, 1), 256>>>(p_wq, DD, 0, o_w, DD, 0, p_uq, DD, 0,
                                          64, DD, DD, 1.0f);
    // 8: sim
    gemm_nt<16><<<dim3(SS / 8, BB), 256>>>(p_uq, DD, (long)HH * DD,
                                           p_vals, DD, (long)SS * DD,
                                           p_sim, SS, (long)HH * SS,
                                           HH, SS, DD, 1.0f / 32.0f);
    // 9: row softmax
    softmax_rows<<<BB * HH, 256>>>(p_sim, SS);
    // 10: wvals
    gemm_nn<16><<<dim3(DD / 256, BB, 8), 256>>>(p_sim, SS, (long)HH * SS,
                                                p_vals, DD, (long)SS * DD,
                                                nullptr, p_wvals, DD, (long)HH * DD,
                                                HH, DD, SS, 1.0f, 0);
    // 11: wtext
    gemm_nn<64><<<dim3(DD / 256, 1, 16), 256>>>(p_wvals, DD, 0, o_w, DD, 0,
                                                nullptr, p_wtext, DD, 0,
                                                64, DD, DD, 1.0f, 0);
    // 12: out_pre
    gemm_nn4<4><<<dim3(1, HH, 8), 256>>>(p_wtext, HH * DD, (long)DD,
                                         ctx_v_w, INNER, 1024L,
                                         p_outpre, INNER, 1024L, BB, DD);
    // 13: out head
    gemm_nn4<4><<<dim3(1, 1, 128), 256>>>(p_outpre, INNER, 0, out_w, DD, 0,
                                          out_head, DD, 0, BB, INNER);
    // 14: ctx_row
    gemm_nn4<4><<<dim3(1, 1, 128), 256>>>(p_vv, INNER, 0, ctx_out_w, DD, 0,
                                          p_ctxrow, DD, 0, BB, INNER);
    // 15-19: tiny MLP
    gemm_nn4<4><<<dim3(DI2 / 1024, 1, 16), 256>>>(p_ctxrow, DD, 0, w1, DI2, 0,
                                                  p_h1, DI2, 0, BB, DD);
    tanh_bias_k<<<(BB * DI2 + 255) / 256, 256>>>(p_h1, b1, DI2, BB * DI2);
    gemm_nn4<4><<<dim3(DI2 / 1024, 1, 32), 256>>>(p_h1, DI2, 0, w2, DI2, 0,
                                                  p_h2, DI2, 0, BB, DI2);
    tanh_bias_k<<<(BB * DI2 + 255) / 256, 256>>>(p_h2, b2, DI2, BB * DI2);
    gemm_nn4<4><<<dim3(1, 1, 32), 256>>>(p_h2, DI2, 0, w3, DD, 0,
                                         p_trow, DD, 0, BB, DI2);
    // 20: broadcast
    bcast_text<<<(BB * SS * DD / 4) / 256, 256>>>(p_trow, b3, out_text);
}

// round 9
// speedup vs baseline: 1.2143x; 1.2143x over previous
#include <cuda_runtime.h>
#include <cuda_bf16.h>
#include <cstdint>
#include <math.h>

#define BB 4
#define SS 1024
#define DD 1024
#define HH 16
#define INNER 16384
#define DI2 2048

// ---- scratch ----
__device__ float g_vals[BB * SS * DD];
__device__ float g_qkimg[BB * INNER];
__device__ float g_vv[BB * INNER];
__device__ float g_wq[BB * HH * DD];
__device__ float g_uq[BB * HH * DD];
__device__ float g_sim[BB * HH * SS];
__device__ float g_wvals[BB * HH * DD];
__device__ float g_wtext[BB * HH * DD];
__device__ float g_outpre[BB * INNER];
__device__ float g_ctxrow[BB * DD];
__device__ float g_h1[BB * DI2];
__device__ float g_h2[BB * DI2];
__device__ float g_trow[BB * DD];
__device__ __nv_bfloat16 g_Ahi[BB * SS * DD];
__device__ __nv_bfloat16 g_Alo[BB * SS * DD];
__device__ __nv_bfloat16 g_Bhi[DD * 3 * DD];
__device__ __nv_bfloat16 g_Blo[DD * 3 * DD];
__device__ __nv_bfloat16 g_qkvhi[BB * SS * 3 * DD];
__device__ __nv_bfloat16 g_qkvlo[BB * SS * 3 * DD];

// ---------------------------------------------------------------------------
__device__ __forceinline__ unsigned s2u(const void* p) {
    return (unsigned)__cvta_generic_to_shared(p);
}
__device__ __forceinline__ void ldsm_x4(unsigned* r, unsigned addr) {
    asm volatile("ldmatrix.sync.aligned.m8n8.x4.shared.b16 {%0,%1,%2,%3}, [%4];"
                 : "=r"(r[0]), "=r"(r[1]), "=r"(r[2]), "=r"(r[3]) : "r"(addr));
}
__device__ __forceinline__ void ldsm_x4t(unsigned* r, unsigned addr) {
    asm volatile("ldmatrix.sync.aligned.m8n8.x4.trans.shared.b16 {%0,%1,%2,%3}, [%4];"
                 : "=r"(r[0]), "=r"(r[1]), "=r"(r[2]), "=r"(r[3]) : "r"(addr));
}
__device__ __forceinline__ void mma_bf16(float* c, const unsigned* a,
                                         unsigned b0, unsigned b1) {
    asm volatile(
        "mma.sync.aligned.m16n8k16.row.col.f32.bf16.bf16.f32 "
        "{%0,%1,%2,%3}, {%4,%5,%6,%7}, {%8,%9}, {%0,%1,%2,%3};"
        : "+f"(c[0]), "+f"(c[1]), "+f"(c[2]), "+f"(c[3])
        : "r"(a[0]), "r"(a[1]), "r"(a[2]), "r"(a[3]), "r"(b0), "r"(b1));
}
__device__ __forceinline__ void cp16(unsigned dst, const void* src) {
    asm volatile("cp.async.cg.shared.global [%0], [%1], 16;" :: "r"(dst), "l"(src));
}
__device__ __forceinline__ void cp_commit() { asm volatile("cp.async.commit_group;"); }
__device__ __forceinline__ void cp_wait1() { asm volatile("cp.async.wait_group 1;"); }
__device__ __forceinline__ void cp_wait0() { asm volatile("cp.async.wait_group 0;"); }
__device__ __forceinline__ unsigned packbf(float x, float y) {
    unsigned short a = __bfloat16_as_ushort(__float2bfloat16(x));
    unsigned short b = __bfloat16_as_ushort(__float2bfloat16(y));
    return (unsigned)a | ((unsigned)b << 16);
}

// ---------------------------------------------------------------------------
__global__ void split2bf16(const float* __restrict__ x,
                           __nv_bfloat16* __restrict__ hi,
                           __nv_bfloat16* __restrict__ lo, int n4) {
    int i = blockIdx.x * 256 + threadIdx.x;
    if (i >= n4) return;
    float4 v = *(const float4*)&x[i * 4];
    __nv_bfloat16 h0 = __float2bfloat16(v.x);
    __nv_bfloat16 h1 = __float2bfloat16(v.y);
    __nv_bfloat16 h2 = __float2bfloat16(v.z);
    __nv_bfloat16 h3 = __float2bfloat16(v.w);
    *(__nv_bfloat162*)&hi[i * 4] = __halves2bfloat162(h0, h1);
    *(__nv_bfloat162*)&hi[i * 4 + 2] = __halves2bfloat162(h2, h3);
    *(__nv_bfloat162*)&lo[i * 4] = __halves2bfloat162(
        __float2bfloat16(v.x - __bfloat162float(h0)),
        __float2bfloat16(v.y - __bfloat162float(h1)));
    *(__nv_bfloat162*)&lo[i * 4 + 2] = __halves2bfloat162(
        __float2bfloat16(v.z - __bfloat162float(h2)),
        __float2bfloat16(v.w - __bfloat162float(h3)));
}

// ---------------------------------------------------------------------------
// bf16x3 tensor-core GEMM, 3-stage cp.async ring (reverted: proven 250us).
#define LDA_S 40
#define LDB_S 136
#define STAGE_ELEMS (128 * LDA_S * 2 + 32 * LDB_S * 2)
#define GEMM_SMEM (3 * STAGE_ELEMS * 2)

#define LOAD_STAGE(S, K0)                                                              \
    do {                                                                               \
        __nv_bfloat16* _b = smem + (S) * STAGE_ELEMS;                                  \
        cp16(s2u(_b + aR0 * LDA_S + aC0), Ahi + (size_t)(rowBase + aR0) * K + (K0) + aC0); \
        cp16(s2u(_b + aR1 * LDA_S + aC1), Ahi + (size_t)(rowBase + aR1) * K + (K0) + aC1); \
        cp16(s2u(_b + 128 * LDA_S + aR0 * LDA_S + aC0), Alo + (size_t)(rowBase + aR0) * K + (K0) + aC0); \
        cp16(s2u(_b + 128 * LDA_S + aR1 * LDA_S + aC1), Alo + (size_t)(rowBase + aR1) * K + (K0) + aC1); \
        cp16(s2u(_b + 256 * LDA_S + bR0 * LDB_S + bC0), Bhi + (size_t)((K0) + bR0) * N + colBase + bC0); \
        cp16(s2u(_b + 256 * LDA_S + bR1 * LDB_S + bC1), Bhi + (size_t)((K0) + bR1) * N + colBase + bC1); \
        cp16(s2u(_b + 256 * LDA_S + 32 * LDB_S + bR0 * LDB_S + bC0), Blo + (size_t)((K0) + bR0) * N + colBase + bC0); \
        cp16(s2u(_b + 256 * LDA_S + 32 * LDB_S + bR1 * LDB_S + bC1), Blo + (size_t)((K0) + bR1) * N + colBase + bC1); \
        cp_commit();                                                                   \
    } while (0)

__global__ __launch_bounds__(256) void gemm_bf16x3(
    const __nv_bfloat16* __restrict__ Ahi, const __nv_bfloat16* __restrict__ Alo,
    const __nv_bfloat16* __restrict__ Bhi, const __nv_bfloat16* __restrict__ Blo,
    const float* __restrict__ bias,
    __nv_bfloat16* __restrict__ Chi, __nv_bfloat16* __restrict__ Clo,
    int M, int N, int K) {
    extern __shared__ char dynsm[];
    __nv_bfloat16* smem = (__nv_bfloat16*)dynsm;
    const int tid = threadIdx.x;
    const int warp = tid >> 5, lane = tid & 31;
    const int wm = (warp >> 2) * 64, wn = (warp & 3) * 32;
    const int rowBase = blockIdx.y * 128, colBase = blockIdx.x * 128;

    const int aR0 = (tid * 2) >> 2, aC0 = ((tid * 2) & 3) << 3;
    const int aR1 = (tid * 2 + 1) >> 2, aC1 = ((tid * 2 + 1) & 3) << 3;
    const int bR0 = (tid * 2) >> 4, bC0 = ((tid * 2) & 15) << 3;
    const int bR1 = (tid * 2 + 1) >> 4, bC1 = ((tid * 2 + 1) & 15) << 3;

    float cacc[4][4][4];
#pragma unroll
    for (int i = 0; i < 4; i++)
#pragma unroll
        for (int j = 0; j < 4; j++)
#pragma unroll
            for (int v = 0; v < 4; v++) cacc[i][j][v] = 0.f;

    const int nIter = K / 32;
    LOAD_STAGE(0, 0);
    LOAD_STAGE(1, 32);

    for (int it = 0; it < nIter; it++) {
        if (it + 1 < nIter) cp_wait1(); else cp_wait0();
        __syncthreads();
        if (it + 2 < nIter) {
            LOAD_STAGE((it + 2) % 3, (it + 2) * 32);
        }
        const int cur = it % 3;
        __nv_bfloat16* sAh = smem + cur * STAGE_ELEMS;
        __nv_bfloat16* sAl = sAh + 128 * LDA_S;
        __nv_bfloat16* sBh = sAh + 256 * LDA_S;
        __nv_bfloat16* sBl = sAh + 256 * LDA_S + 32 * LDB_S;

#pragma unroll
        for (int ks = 0; ks < 32; ks += 16) {
            unsigned ah[4][4], al[4][4], bh[2][4], bl[2][4];
            const int arow = (lane & 15);
            const int acol = ks + ((lane >> 4) << 3);
#pragma unroll
            for (int mt = 0; mt < 4; mt++) {
                int off = (wm + mt * 16 + arow) * LDA_S + acol;
                ldsm_x4(ah[mt], s2u(sAh + off));
                ldsm_x4(al[mt], s2u(sAl + off));
            }
            const int brow = ks + (lane & 15);
            const int bcol0 = wn + ((lane >> 4) << 3);
#pragma unroll
            for (int nt = 0; nt < 2; nt++) {
                int off = brow * LDB_S + bcol0 + nt * 16;
                ldsm_x4t(bh[nt], s2u(sBh + off));
                ldsm_x4t(bl[nt], s2u(sBl + off));
            }
#pragma unroll
            for (int mt = 0; mt < 4; mt++) {
#pragma unroll
                for (int j = 0; j < 4; j++) {
                    unsigned bh0 = bh[j >> 1][(j & 1) * 2], bh1 = bh[j >> 1][(j & 1) * 2 + 1];
                    unsigned bl0 = bl[j >> 1][(j & 1) * 2], bl1 = bl[j >> 1][(j & 1) * 2 + 1];
                    mma_bf16(cacc[mt][j], ah[mt], bh0, bh1);
                    mma_bf16(cacc[mt][j], ah[mt], bl0, bl1);
                    mma_bf16(cacc[mt][j], al[mt], bh0, bh1);
                }
            }
        }
    }

#pragma unroll
    for (int mt = 0; mt < 4; mt++) {
#pragma unroll
        for (int j = 0; j < 4; j++) {
            int r0 = rowBase + wm + mt * 16 + (lane >> 2);
            int c0 = colBase + wn + j * 8 + (lane & 3) * 2;
            float b0 = bias[c0], b1 = bias[c0 + 1];
#pragma unroll
            for (int half = 0; half < 2; half++) {
                int r = r0 + half * 8;
                float x = cacc[mt][j][half * 2 + 0] + b0;
                float y = cacc[mt][j][half * 2 + 1] + b1;
                __nv_bfloat16 hx = __float2bfloat16(x);
                __nv_bfloat16 hy = __float2bfloat16(y);
                *(__nv_bfloat162*)&Chi[(size_t)r * N + c0] = __halves2bfloat162(hx, hy);
                *(__nv_bfloat162*)&Clo[(size_t)r * N + c0] = __halves2bfloat162(
                    __float2bfloat16(x - __bfloat162float(hx)),
                    __float2bfloat16(y - __bfloat162float(hy)));
            }
        }
    }
}

// ---------------------------------------------------------------------------
// Tensor-core flash attention (bf16x3). Scale folded into exp/max.
#define SA 72
#define ATT_STAGE (4 * 64 * SA)
#define ATT_SMEM ((2 * 64 * SA + 2 * ATT_STAGE) * 2)

__global__ __launch_bounds__(128) void attn3(const __nv_bfloat16* __restrict__ qkvhi,
                                             const __nv_bfloat16* __restrict__ qkvlo,
                                             float* __restrict__ vals) {
    extern __shared__ char dynsm[];
    __nv_bfloat16* SM = (__nv_bfloat16*)dynsm;
    __nv_bfloat16* Qhi = SM;
    __nv_bfloat16* Qlo = SM + 64 * SA;
    const int tid = threadIdx.x;
    const int warp = tid >> 5, lane = tid & 31;
    const int b = blockIdx.x >> 4, h = blockIdx.x & 15;
    const int qbase = blockIdx.y * 64;
    const size_t gbase = (size_t)b * SS * 3072 + h * 192;

    {
#pragma unroll
        for (int i = 0; i < 4; i++) {
            int c = i * 128 + tid;
            int row = c >> 3, col = (c & 7) << 3;
            size_t src = gbase + (size_t)(qbase + row) * 3072 + col;
            cp16(s2u(Qhi + row * SA + col), qkvhi + src);
            cp16(s2u(Qlo + row * SA + col), qkvlo + src);
        }
        __nv_bfloat16* st = SM + 2 * 64 * SA;
#pragma unroll
        for (int i = 0; i < 4; i++) {
            int c = i * 128 + tid;
            int row = c >> 3, col = (c & 7) << 3;
            size_t srcK = gbase + (size_t)row * 3072 + 64 + col;
            size_t srcV = gbase + (size_t)row * 3072 + 128 + col;
            cp16(s2u(st + row * SA + col), qkvhi + srcK);
            cp16(s2u(st + 64 * SA + row * SA + col), qkvlo + srcK);
            cp16(s2u(st + 2 * 64 * SA + row * SA + col), qkvhi + srcV);
            cp16(s2u(st + 3 * 64 * SA + row * SA + col), qkvlo + srcV);
        }
        cp_commit();
    }

    unsigned qh[4][4], ql[4][4];
    float o[8][4];
    float m0 = -1e30f, m1 = -1e30f, l0 = 0.f, l1 = 0.f;
#pragma unroll
    for (int i = 0; i < 8; i++)
#pragma unroll
        for (int j = 0; j < 4; j++) o[i][j] = 0.f;

    const int NT = SS / 64;
    for (int t = 0; t < NT; t++) {
        const int cur = t & 1;
        if (t + 1 < NT) {
            __nv_bfloat16* st = SM + 2 * 64 * SA + (cur ^ 1) * ATT_STAGE;
            const int kv0 = (t + 1) * 64;
#pragma unroll
            for (int i = 0; i < 4; i++) {
                int c = i * 128 + tid;
                int row = c >> 3, col = (c & 7) << 3;
                size_t srcK = gbase + (size_t)(kv0 + row) * 3072 + 64 + col;
                size_t srcV = gbase + (size_t)(kv0 + row) * 3072 + 128 + col;
                cp16(s2u(st + row * SA + col), qkvhi + srcK);
                cp16(s2u(st + 64 * SA + row * SA + col), qkvlo + srcK);
                cp16(s2u(st + 2 * 64 * SA + row * SA + col), qkvhi + srcV);
                cp16(s2u(st + 3 * 64 * SA + row * SA + col), qkvlo + srcV);
            }
            cp_commit();
            cp_wait1();
        } else {
            cp_wait0();
        }
        __syncthreads();

        if (t == 0) {
#pragma unroll
            for (int kt = 0; kt < 4; kt++) {
                int off = (warp * 16 + (lane & 15)) * SA + kt * 16 + ((lane >> 4) << 3);
                ldsm_x4(qh[kt], s2u(Qhi + off));
                ldsm_x4(ql[kt], s2u(Qlo + off));
            }
        }

        __nv_bfloat16* sKh = SM + 2 * 64 * SA + cur * ATT_STAGE;
        __nv_bfloat16* sKl = sKh + 64 * SA;
        __nv_bfloat16* sVh = sKh + 2 * 64 * SA;
        __nv_bfloat16* sVl = sKh + 3 * 64 * SA;

        float sc[8][4];
#pragma unroll
        for (int n = 0; n < 8; n++)
#pragma unroll
            for (int v = 0; v < 4; v++) sc[n][v] = 0.f;
#pragma unroll
        for (int kt = 0; kt < 4; kt++) {
            unsigned kh[4][4], kl[4][4];
#pragma unroll
            for (int nt = 0; nt < 4; nt++) {
                int off = (nt * 16 + (lane & 15)) * SA + kt * 16 + ((lane >> 4) << 3);
                ldsm_x4(kh[nt], s2u(sKh + off));
                ldsm_x4(kl[nt], s2u(sKl + off));
            }
#pragma unroll
            for (int nt = 0; nt < 4; nt++) {
#pragma unroll
                for (int sub = 0; sub < 2; sub++) {
                    int n = nt * 2 + sub;
                    mma_bf16(sc[n], qh[kt], kh[nt][sub], kh[nt][sub + 2]);
                    mma_bf16(sc[n], qh[kt], kl[nt][sub], kl[nt][sub + 2]);
                    mma_bf16(sc[n], ql[kt], kh[nt][sub], kh[nt][sub + 2]);
                }
            }
        }

        float mt0 = -1e30f, mt1 = -1e30f;
#pragma unroll
        for (int n = 0; n < 8; n++) {
            mt0 = fmaxf(mt0, fmaxf(sc[n][0], sc[n][1]));
            mt1 = fmaxf(mt1, fmaxf(sc[n][2], sc[n][3]));
        }
        mt0 = fmaxf(mt0, __shfl_xor_sync(0xffffffffu, mt0, 1));
        mt0 = fmaxf(mt0, __shfl_xor_sync(0xffffffffu, mt0, 2));
        mt1 = fmaxf(mt1, __shfl_xor_sync(0xffffffffu, mt1, 1));
        mt1 = fmaxf(mt1, __shfl_xor_sync(0xffffffffu, mt1, 2));
        float mn0 = fmaxf(m0, mt0), mn1 = fmaxf(m1, mt1);
        float cr0 = __expf(0.125f * (m0 - mn0));
        float cr1 = __expf(0.125f * (m1 - mn1));
        float nb0 = -0.125f * mn0, nb1 = -0.125f * mn1;
        float s0 = 0.f, s1 = 0.f;
#pragma unroll
        for (int n = 0; n < 8; n++) {
            sc[n][0] = __expf(fmaf(sc[n][0], 0.125f, nb0));
            sc[n][1] = __expf(fmaf(sc[n][1], 0.125f, nb0));
            sc[n][2] = __expf(fmaf(sc[n][2], 0.125f, nb1));
            sc[n][3] = __expf(fmaf(sc[n][3], 0.125f, nb1));
            s0 += sc[n][0] + sc[n][1];
            s1 += sc[n][2] + sc[n][3];
        }
        s0 += __shfl_xor_sync(0xffffffffu, s0, 1);
        s0 += __shfl_xor_sync(0xffffffffu, s0, 2);
        s1 += __shfl_xor_sync(0xffffffffu, s1, 1);
        s1 += __shfl_xor_sync(0xffffffffu, s1, 2);
        l0 = l0 * cr0 + s0; l1 = l1 * cr1 + s1;
        m0 = mn0; m1 = mn1;
#pragma unroll
        for (int d = 0; d < 8; d++) {
            o[d][0] *= cr0; o[d][1] *= cr0;
            o[d][2] *= cr1; o[d][3] *= cr1;
        }

        unsigned ph[4][4], pl[4][4];
#pragma unroll
        for (int kt2 = 0; kt2 < 4; kt2++) {
#pragma unroll
            for (int part = 0; part < 4; part++) {
                int n = kt2 * 2 + (part >> 1);
                int i0 = (part & 1) * 2;
                float x = sc[n][i0], y = sc[n][i0 + 1];
                __nv_bfloat16 hx = __float2bfloat16(x);
                __nv_bfloat16 hy = __float2bfloat16(y);
                ph[kt2][part] = (unsigned)__bfloat16_as_ushort(hx) |
                                ((unsigned)__bfloat16_as_ushort(hy) << 16);
                pl[kt2][part] = packbf(x - __bfloat162float(hx),
                                       y - __bfloat162float(hy));
            }
        }

#pragma unroll
        for (int kt2 = 0; kt2 < 4; kt2++) {
            unsigned vh[4][4], vl[4][4];
#pragma unroll
            for (int dt = 0; dt < 4; dt++) {
                int off = (kt2 * 16 + (lane & 15)) * SA + dt * 16 + ((lane >> 4) << 3);
                ldsm_x4t(vh[dt], s2u(sVh + off));
                ldsm_x4t(vl[dt], s2u(sVl + off));
            }
#pragma unroll
            for (int dt = 0; dt < 4; dt++) {
#pragma unroll
                for (int sub = 0; sub < 2; sub++) {
                    int d = dt * 2 + sub;
                    mma_bf16(o[d], ph[kt2], vh[dt][sub * 2], vh[dt][sub * 2 + 1]);
                    mma_bf16(o[d], ph[kt2], vl[dt][sub * 2], vl[dt][sub * 2 + 1]);
                    mma_bf16(o[d], pl[kt2], vh[dt][sub * 2], vh[dt][sub * 2 + 1]);
                }
            }
        }
        __syncthreads();
    }

    float inv0 = 1.f / l0, inv1 = 1.f / l1;
    int row0 = qbase + warp * 16 + (lane >> 2);
    int row1 = row0 + 8;
#pragma unroll
    for (int d = 0; d < 8; d++) {
        int c0 = h * 64 + d * 8 + (lane & 3) * 2;
        float2 v0; v0.x = o[d][0] * inv0; v0.y = o[d][1] * inv0;
        float2 v1; v1.x = o[d][2] * inv1; v1.y = o[d][3] * inv1;
        *(float2*)&vals[(size_t)(b * SS + row0) * DD + c0] = v0;
        *(float2*)&vals[(size_t)(b * SS + row1) * DD + c0] = v1;
    }
}

// ---------------------------------------------------------------------------
__global__ void init_all(float* __restrict__ qkimg, float* __restrict__ vv,
                         float* __restrict__ outpre, float* __restrict__ wvals,
                         float* __restrict__ h1, float* __restrict__ h2,
                         float* __restrict__ trow,
                         float* __restrict__ outh, const float* __restrict__ out_b,
                         float* __restrict__ ctxrow, const float* __restrict__ ctx_out_b,
                         float* __restrict__ wtext, const float* __restrict__ o_b) {
    int i = blockIdx.x * 256 + threadIdx.x;
    qkimg[i] = 0.f; vv[i] = 0.f; outpre[i] = 0.f; wvals[i] = 0.f;
    wtext[i] = o_b[i & 1023];
    if (i < BB * DI2) { h1[i] = 0.f; h2[i] = 0.f; }
    if (i < BB * DD) {
        trow[i] = 0.f;
        outh[i] = out_b[i & 1023];
        ctxrow[i] = ctx_out_b[i & 1023];
    }
}

// ---------------------------------------------------------------------------
__global__ void img_proj(const float* __restrict__ img,
                         const float* __restrict__ W1, const float* __restrict__ W2,
                         float* __restrict__ O1, float* __restrict__ O2) {
    const float* W = blockIdx.z ? W2 : W1;
    float* O = blockIdx.z ? O2 : O1;
    int col = blockIdx.x * 256 + threadIdx.x;
    int k0 = blockIdx.y * 128;
    __shared__ float xs[4][128];
    for (int i = threadIdx.x; i < 512; i += 256)
        xs[i >> 7][i & 127] = img[(i >> 7) * DD + k0 + (i & 127)];
    __syncthreads();
    float a0 = 0, a1 = 0, a2 = 0, a3 = 0;
    const float* wp = W + (size_t)k0 * INNER + col;
#pragma unroll 4
    for (int k = 0; k < 128; k++) {
        float wv = wp[(size_t)k * INNER];
        a0 += xs[0][k] * wv; a1 += xs[1][k] * wv;
        a2 += xs[2][k] * wv; a3 += xs[3][k] * wv;
    }
    atomicAdd(&O[col], a0);
    atomicAdd(&O[INNER + col], a1);
    atomicAdd(&O[2 * INNER + col], a2);
    atomicAdd(&O[3 * INNER + col], a3);
}

// ---------------------------------------------------------------------------
__global__ __launch_bounds__(256) void wq_kernel(const float* __restrict__ Wc,
                                                 const float* __restrict__ qkimg,
                                                 float* __restrict__ wq) {
    int gwarp = (blockIdx.x * 256 + threadIdx.x) >> 5;
    int lane = threadIdx.x & 31;
    int d = gwarp >> 4, h = gwarp & 15;
    const float* row = Wc + (size_t)d * INNER + h * 1024;
    const float* qb = qkimg + h * 1024;
    float a0 = 0, a1 = 0, a2 = 0, a3 = 0;
    for (int e = lane; e < 1024; e += 32) {
        float wv = row[e];
        a0 += wv * qb[e];
        a1 += wv * qb[INNER + e];
        a2 += wv * qb[2 * INNER + e];
        a3 += wv * qb[3 * INNER + e];
    }
#pragma unroll
    for (int o = 16; o; o >>= 1) {
        a0 += __shfl_xor_sync(0xffffffffu, a0, o);
        a1 += __shfl_xor_sync(0xffffffffu, a1, o);
        a2 += __shfl_xor_sync(0xffffffffu, a2, o);
        a3 += __shfl_xor_sync(0xffffffffu, a3, o);
    }
    if (lane == 0) {
        wq[(0 * HH + h) * DD + d] = a0;
        wq[(1 * HH + h) * DD + d] = a1;
        wq[(2 * HH + h) * DD + d] = a2;
        wq[(3 * HH + h) * DD + d] = a3;
    }
}

// ---------------------------------------------------------------------------
template <int MT>
__global__ __launch_bounds__(256) void gemm_nt(const float* __restrict__ A, int lda, long sA,
                                               const float* __restrict__ Bm, int ldb, long sB,
                                               float* __restrict__ C, int ldc, long sC,
                                               int M, int N, int K, float alpha) {
    int batch = blockIdx.y;
    A += (size_t)batch * sA; Bm += (size_t)batch * sB; C += (size_t)batch * sC;
    int warp = threadIdx.x >> 5, lane = threadIdx.x & 31;
    int j = blockIdx.x * 8 + warp;
    __shared__ float As[MT][128];
    float acc[MT];
#pragma unroll
    for (int i = 0; i < MT; i++) acc[i] = 0.f;
    for (int k0 = 0; k0 < K; k0 += 128) {
        __syncthreads();
        for (int i = threadIdx.x; i < MT * 128; i += 256) {
            int r = i >> 7, c = i & 127;
            As[r][c] = (r < M) ? A[(size_t)r * lda + k0 + c] : 0.f;
        }
        __syncthreads();
        const float* bp = Bm + (size_t)j * ldb + k0;
        for (int k = lane; k < 128; k += 32) {
            float bv = bp[k];
#pragma unroll
            for (int i = 0; i < MT; i++) acc[i] += As[i][k] * bv;
        }
    }
#pragma unroll
    for (int i = 0; i < MT; i++) {
        float v = acc[i];
#pragma unroll
        for (int o = 16; o; o >>= 1) v += __shfl_xor_sync(0xffffffffu, v, o);
        if (lane == 0 && i < M) C[(size_t)i * ldc + j] = alpha * v;
    }
}

// ---------------------------------------------------------------------------
template <int MT>
__global__ __launch_bounds__(256) void gemm_nn(const float* __restrict__ A, int lda, long sA,
                                               const float* __restrict__ Bm, int ldb, long sB,
                                               const float* __restrict__ bias,
                                               float* __restrict__ C, int ldc, long sC,
                                               int M, int N, int K, float alpha, int act) {
    int batch = blockIdx.y;
    A += (size_t)batch * sA; Bm += (size_t)batch * sB; C += (size_t)batch * sC;
    int j = blockIdx.x * 256 + threadIdx.x;
    int kChunk = K / gridDim.z;
    int kBeg = blockIdx.z * kChunk;
    float acc[MT];
#pragma unroll
    for (int i = 0; i < MT; i++) acc[i] = 0.f;
    __shared__ float As[MT][32];
    for (int k0 = kBeg; k0 < kBeg + kChunk; k0 += 32) {
        __syncthreads();
        for (int i = threadIdx.x; i < MT * 32; i += 256) {
            int r = i >> 5, c = i & 31;
            As[r][c] = (r < M) ? A[(size_t)r * lda + k0 + c] : 0.f;
        }
        __syncthreads();
#pragma unroll 4
        for (int k = 0; k < 32; k++) {
            float bv = Bm[(size_t)(k0 + k) * ldb + j];
#pragma unroll
            for (int i = 0; i < MT; i++) acc[i] += As[i][k] * bv;
        }
    }
    if (gridDim.z == 1) {
        float bb = bias ? bias[j] : 0.f;
        for (int i = 0; i < MT && i < M; i++) {
            float v = alpha * acc[i] + bb;
            if (act) v = tanhf(v);
            C[(size_t)i * ldc + j] = v;
        }
    } else {
        for (int i = 0; i < MT && i < M; i++)
            atomicAdd(&C[(size_t)i * ldc + j], alpha * acc[i]);
    }
}

// ---------------------------------------------------------------------------
template <int MT>
__global__ __launch_bounds__(256) void gemm_nn4(const float* __restrict__ A, int lda, long sA,
                                                const float* __restrict__ Bm, int ldb, long sB,
                                                float* __restrict__ C, int ldc, long sC,
                                                int M, int K) {
    int batch = blockIdx.y;
    A += (size_t)batch * sA; Bm += (size_t)batch * sB; C += (size_t)batch * sC;
    int j4 = (blockIdx.x * 256 + threadIdx.x) * 4;
    int kChunk = K / gridDim.z;
    int kBeg = blockIdx.z * kChunk;
    float acc[MT][4];
#pragma unroll
    for (int i = 0; i < MT; i++) {
        acc[i][0] = 0.f; acc[i][1] = 0.f; acc[i][2] = 0.f; acc[i][3] = 0.f;
    }
    __shared__ float As[MT][32];
    for (int k0 = kBeg; k0 < kBeg + kChunk; k0 += 32) {
        __syncthreads();
        for (int i = threadIdx.x; i < MT * 32; i += 256) {
            int r = i >> 5, c = i & 31;
            As[r][c] = (r < M) ? A[(size_t)r * lda + k0 + c] : 0.f;
        }
        __syncthreads();
#pragma unroll 8
        for (int k = 0; k < 32; k++) {
            float4 bv = *(const float4*)&Bm[(size_t)(k0 + k) * ldb + j4];
#pragma unroll
            for (int i = 0; i < MT; i++) {
                float a = As[i][k];
                acc[i][0] += a * bv.x; acc[i][1] += a * bv.y;
                acc[i][2] += a * bv.z; acc[i][3] += a * bv.w;
            }
        }
    }
    for (int i = 0; i < MT && i < M; i++) {
        atomicAdd(&C[(size_t)i * ldc + j4 + 0], acc[i][0]);
        atomicAdd(&C[(size_t)i * ldc + j4 + 1], acc[i][1]);
        atomicAdd(&C[(size_t)i * ldc + j4 + 2], acc[i][2]);
        atomicAdd(&C[(size_t)i * ldc + j4 + 3], acc[i][3]);
    }
}

// ---------------------------------------------------------------------------
__global__ void softmax_rows(float* __restrict__ base, int n) {
    float* p = base + (size_t)blockIdx.x * n;
    __shared__ float red[8];
    __shared__ float red2[8];
    int tid = threadIdx.x;
    float m = -1e30f;
    for (int j = tid; j < n; j += 256) m = fmaxf(m, p[j]);
#pragma unroll
    for (int o = 16; o; o >>= 1) m = fmaxf(m, __shfl_xor_sync(0xffffffffu, m, o));
    if ((tid & 31) == 0) red[tid >> 5] = m;
    __syncthreads();
    float mm = red[0];
#pragma unroll
    for (int w = 1; w < 8; w++) mm = fmaxf(mm, red[w]);
    float sum = 0.f;
    for (int j = tid; j < n; j += 256) {
        float e = __expf(p[j] - mm);
        p[j] = e;
        sum += e;
    }
#pragma unroll
    for (int o = 16; o; o >>= 1) sum += __shfl_xor_sync(0xffffffffu, sum, o);
    if ((tid & 31) == 0) red2[tid >> 5] = sum;
    __syncthreads();
    float tot = 0.f;
#pragma unroll
    for (int w = 0; w < 8; w++) tot += red2[w];
    float inv = 1.f / tot;
    for (int j = tid; j < n; j += 256) p[j] *= inv;
}

// ---------------------------------------------------------------------------
__global__ void tanh_bias_k(float* __restrict__ x, const float* __restrict__ bias,
                            int n, int total) {
    int i = blockIdx.x * 256 + threadIdx.x;
    if (i < total) x[i] = tanhf(x[i] + bias[i % n]);
}

__global__ void bcast_text(const float* __restrict__ trow, const float* __restrict__ b3,
                           float* __restrict__ out) {
    size_t idx = (size_t)blockIdx.x * 256 + threadIdx.x;
    size_t e = idx * 4;
    int b = (int)(e / ((size_t)SS * DD));
    int d = (int)(e % DD);
    float4 t = *(const float4*)&trow[b * DD + d];
    float4 bb = *(const float4*)&b3[d];
    t.x += bb.x; t.y += bb.y; t.z += bb.z; t.w += bb.w;
    *(float4*)&out[e] = t;
}

// ---------------------------------------------------------------------------
extern "C" void kernel_launch(void* const* d_in, const int* in_sizes, int n_in,
                              void* d_out, int out_size) {
    (void)in_sizes; (void)n_in; (void)out_size;
    const float* img      = (const float*)d_in[0];
    const float* text_emb = (const float*)d_in[1];
    const float* qkv_w    = (const float*)d_in[2];
    const float* qkv_b    = (const float*)d_in[3];
    const float* o_w      = (const float*)d_in[4];
    const float* o_b      = (const float*)d_in[5];
    const float* qk_w     = (const float*)d_in[6];
    const float* ctx_qk_w = (const float*)d_in[7];
    const float* v_w      = (const float*)d_in[8];
    const float* ctx_v_w  = (const float*)d_in[9];
    const float* out_w    = (const float*)d_in[10];
    const float* out_b    = (const float*)d_in[11];
    const float* ctx_out_w= (const float*)d_in[12];
    const float* ctx_out_b= (const float*)d_in[13];
    const float* w1 = (const float*)d_in[14];
    const float* b1 = (const float*)d_in[15];
    const float* w2 = (const float*)d_in[16];
    const float* b2 = (const float*)d_in[17];
    const float* w3 = (const float*)d_in[18];
    const float* b3 = (const float*)d_in[19];

    float* out_head = (float*)d_out;
    float* out_text = (float*)d_out + BB * DD;

    float* p_vals;   cudaGetSymbolAddress((void**)&p_vals, g_vals);
    float* p_qkimg;  cudaGetSymbolAddress((void**)&p_qkimg, g_qkimg);
    float* p_vv;     cudaGetSymbolAddress((void**)&p_vv, g_vv);
    float* p_wq;     cudaGetSymbolAddress((void**)&p_wq, g_wq);
    float* p_uq;     cudaGetSymbolAddress((void**)&p_uq, g_uq);
    float* p_sim;    cudaGetSymbolAddress((void**)&p_sim, g_sim);
    float* p_wvals;  cudaGetSymbolAddress((void**)&p_wvals, g_wvals);
    float* p_wtext;  cudaGetSymbolAddress((void**)&p_wtext, g_wtext);
    float* p_outpre; cudaGetSymbolAddress((void**)&p_outpre, g_outpre);
    float* p_ctxrow; cudaGetSymbolAddress((void**)&p_ctxrow, g_ctxrow);
    float* p_h1;     cudaGetSymbolAddress((void**)&p_h1, g_h1);
    float* p_h2;     cudaGetSymbolAddress((void**)&p_h2, g_h2);
    float* p_trow;   cudaGetSymbolAddress((void**)&p_trow, g_trow);
    __nv_bfloat16* p_Ahi; cudaGetSymbolAddress((void**)&p_Ahi, g_Ahi);
    __nv_bfloat16* p_Alo; cudaGetSymbolAddress((void**)&p_Alo, g_Alo);
    __nv_bfloat16* p_Bhi; cudaGetSymbolAddress((void**)&p_Bhi, g_Bhi);
    __nv_bfloat16* p_Blo; cudaGetSymbolAddress((void**)&p_Blo, g_Blo);
    __nv_bfloat16* p_Qkvhi; cudaGetSymbolAddress((void**)&p_Qkvhi, g_qkvhi);
    __nv_bfloat16* p_Qkvlo; cudaGetSymbolAddress((void**)&p_Qkvlo, g_qkvlo);

    static cudaStream_t sB = nullptr;
    static cudaEvent_t evFork = nullptr, evUq = nullptr, evB = nullptr;
    static bool inited = false;
    if (!inited) {
        cudaFuncSetAttribute((const void*)attn3,
                             cudaFuncAttributeMaxDynamicSharedMemorySize, ATT_SMEM);
        cudaFuncSetAttribute((const void*)gemm_bf16x3,
                             cudaFuncAttributeMaxDynamicSharedMemorySize, GEMM_SMEM);
        cudaStreamCreateWithFlags(&sB, cudaStreamNonBlocking);
        cudaEventCreateWithFlags(&evFork, cudaEventDisableTiming);
        cudaEventCreateWithFlags(&evUq, cudaEventDisableTiming);
        cudaEventCreateWithFlags(&evB, cudaEventDisableTiming);
        inited = true;
    }

    // ---- fork side stream B off the (captured) default stream ----
    cudaEventRecord(evFork, 0);
    cudaStreamWaitEvent(sB, evFork, 0);

    // ======== stream B: img/cross-attn prep + full text-output chain ========
    init_all<<<256, 256, 0, sB>>>(p_qkimg, p_vv, p_outpre, p_wvals, p_h1, p_h2,
                                  p_trow, out_head, out_b, p_ctxrow, ctx_out_b,
                                  p_wtext, o_b);
    img_proj<<<dim3(INNER / 256, 8, 2), 256, 0, sB>>>(img, qk_w, v_w, p_qkimg, p_vv);
    wq_kernel<<<2048, 256, 0, sB>>>(ctx_qk_w, p_qkimg, p_wq);
    gemm_nt<64><<<dim3(DD / 8, 1), 256, 0, sB>>>(p_wq, DD, 0, o_w, DD, 0,
                                                 p_uq, DD, 0, 64, DD, DD, 1.0f);
    cudaEventRecord(evUq, sB);   // uq + all inits ready for main stream
    // text chain (independent of attention)
    gemm_nn4<4><<<dim3(1, 1, 128), 256, 0, sB>>>(p_vv, INNER, 0, ctx_out_w, DD, 0,
                                                 p_ctxrow, DD, 0, BB, INNER);
    gemm_nn4<4><<<dim3(DI2 / 1024, 1, 16), 256, 0, sB>>>(p_ctxrow, DD, 0, w1, DI2, 0,
                                                         p_h1, DI2, 0, BB, DD);
    tanh_bias_k<<<(BB * DI2 + 255) / 256, 256, 0, sB>>>(p_h1, b1, DI2, BB * DI2);
    gemm_nn4<4><<<dim3(DI2 / 1024, 1, 32), 256, 0, sB>>>(p_h1, DI2, 0, w2, DI2, 0,
                                                         p_h2, DI2, 0, BB, DI2);
    tanh_bias_k<<<(BB * DI2 + 255) / 256, 256, 0, sB>>>(p_h2, b2, DI2, BB * DI2);
    gemm_nn4<4><<<dim3(1, 1, 32), 256, 0, sB>>>(p_h2, DI2, 0, w3, DD, 0,
                                                p_trow, DD, 0, BB, DI2);
    bcast_text<<<(BB * SS * DD / 4) / 256, 256, 0, sB>>>(p_trow, b3, out_text);
    cudaEventRecord(evB, sB);

    // ======== main stream: self-attn + head-output chain ========
    split2bf16<<<(BB * SS * DD / 4 + 255) / 256, 256>>>(text_emb, p_Ahi, p_Alo,
                                                        BB * SS * DD / 4);
    split2bf16<<<(DD * 3 * DD / 4 + 255) / 256, 256>>>(qkv_w, p_Bhi, p_Blo,
                                                       DD * 3 * DD / 4);
    gemm_bf16x3<<<dim3(3072 / 128, 4096 / 128), 256, GEMM_SMEM>>>(
        p_Ahi, p_Alo, p_Bhi, p_Blo, qkv_b, p_Qkvhi, p_Qkvlo, BB * SS, 3 * DD, DD);
    attn3<<<dim3(BB * HH, SS / 64), 128, ATT_SMEM>>>(p_Qkvhi, p_Qkvlo, p_vals);

    cudaStreamWaitEvent(0, evUq, 0);   // need uq + inits
    gemm_nt<16><<<dim3(SS / 8, BB), 256>>>(p_uq, DD, (long)HH * DD,
                                           p_vals, DD, (long)SS * DD,
                                           p_sim, SS, (long)HH * SS,
                                           HH, SS, DD, 1.0f / 32.0f);
    softmax_rows<<<BB * HH, 256>>>(p_sim, SS);
    gemm_nn<16><<<dim3(DD / 256, BB, 8), 256>>>(p_sim, SS, (long)HH * SS,
                                                p_vals, DD, (long)SS * DD,
                                                nullptr, p_wvals, DD, (long)HH * DD,
                                                HH, DD, SS, 1.0f, 0);
    gemm_nn<64><<<dim3(DD / 256, 1, 16), 256>>>(p_wvals, DD, 0, o_w, DD, 0,
                                                nullptr, p_wtext, DD, 0,
                                                64, DD, DD, 1.0f, 0);
    gemm_nn4<4><<<dim3(1, HH, 8), 256>>>(p_wtext, HH * DD, (long)DD,
                                         ctx_v_w, INNER, 1024L,
                                         p_outpre, INNER, 1024L, BB, DD);
    gemm_nn4<4><<<dim3(1, 1, 128), 256>>>(p_outpre, INNER, 0, out_w, DD, 0,
                                          out_head, DD, 0, BB, INNER);
    cudaStreamWaitEvent(0, evB, 0);    // join side chain before returning
}